// round 8
// baseline (speedup 1.0000x reference)
#include <cuda_runtime.h>
#include <cuda_bf16.h>

// Problem constants (fixed by the reference)
#define BG   128              // graphs
#define NN_  512              // nodes per graph
#define FF   128              // feature dim
#define DEG  16
#define ETOT (BG*NN_*DEG)     // 1,048,576 edges
#define NTOT (BG*NN_)         // 65,536 nodes
#define ADJ_WORDS (BG*NN_*(NN_/32))  // 4MB bitmask
#define PADN 64               // padded neighbor-list stride (multiple of 4)

// -------- device-global scratch (no allocations allowed) --------
__device__ unsigned int   g_adj[ADJ_WORDS];
__device__ unsigned short g_nbr[(size_t)NTOT * PADN];  // offsets = node*8 (16B units)
__device__ short          g_cnt[NTOT];                  // cnt4 (padded to mult of 4)
__device__ float          g_dinv[NTOT];
__device__ unsigned int   g_pc[NTOT];                   // degree-sorted: node | cnt4<<16
__device__ float g_acc[(size_t)NTOT * FF];   // 32MB
__device__ float g_y[(size_t)NTOT * FF];     // 32MB
__device__ unsigned int g_wt1[16384];        // W1^T split: hi pairs / lo pairs
__device__ unsigned int g_wt2[16384];        // W2^T split

// ---------------- adjacency build ----------------
__global__ void clear_adj_kernel() {
    int i = blockIdx.x * blockDim.x + threadIdx.x;
    if (i < ADJ_WORDS) g_adj[i] = 0u;
}

__global__ void build_adj_kernel(const int* __restrict__ ei) {
    int e = blockIdx.x * blockDim.x + threadIdx.x;
    if (e >= ETOT) return;
    int src = ei[e];
    int dst = ei[ETOT + e];
    int g  = src >> 9;         // N = 512
    int si = src & 511;
    int di = dst & 511;
    atomicOr(&g_adj[(g * 512 + si) * 16 + (di >> 5)], 1u << (di & 31));
}

// Expand bitmask rows into padded u16 offset lists (node*8, 16B units).
// Zero row lives at node index 512 -> offset 4096. Pad cnt to multiple of 4.
__global__ void expand_kernel() {
    int i = blockIdx.x * blockDim.x + threadIdx.x;   // node id
    if (i >= NTOT) return;
    int cnt = 0;
    unsigned short* row = &g_nbr[(size_t)i * PADN];
#pragma unroll
    for (int w = 0; w < 16; w++) {
        unsigned int bits = g_adj[i * 16 + w];
        while (bits) {
            int b = __ffs(bits) - 1;
            bits &= bits - 1;
            if (cnt < PADN) row[cnt] = (unsigned short)((w * 32 + b) * 8);
            cnt++;
        }
    }
    if (cnt > PADN) cnt = PADN;
    g_dinv[i] = (cnt > 0) ? rsqrtf((float)cnt) : 0.0f;
    int cnt4 = (cnt + 3) & ~3;
    for (int e = cnt; e < cnt4; e++) row[e] = (unsigned short)4096;  // zero row
    g_cnt[i] = (short)cnt4;
}

// Counting sort by degree per graph -> g_pc[g*512 + pos] = node | cnt4<<16
__global__ void __launch_bounds__(512) sort_kernel() {
    __shared__ unsigned hist[17];
    __shared__ unsigned base[17];
    int g = blockIdx.x, tid = threadIdx.x;
    if (tid < 17) hist[tid] = 0;
    __syncthreads();
    int cnt4 = g_cnt[g * 512 + tid];
    int bin = cnt4 >> 2;   // 0..16
    atomicAdd(&hist[bin], 1);
    __syncthreads();
    if (tid == 0) {
        unsigned s = 0;
        for (int i = 0; i < 17; i++) { base[i] = s; s += hist[i]; }
    }
    __syncthreads();
    unsigned pos = atomicAdd(&base[bin], 1);
    g_pc[g * 512 + pos] = (unsigned)tid | ((unsigned)cnt4 << 16);
}

// Transpose + hi/lo bf16 split of both weights in one launch.
__global__ void prep_w_kernel(const float* __restrict__ W1, const float* __restrict__ W2,
                              unsigned int* __restrict__ wt1, unsigned int* __restrict__ wt2) {
    int idx = blockIdx.x * blockDim.x + threadIdx.x;
    const float* W = (idx < 8192) ? W1 : W2;
    unsigned int* wt = (idx < 8192) ? wt1 : wt2;
    int id = idx & 8191;
    int n = id >> 6, k = (id & 63) * 2;
    float x0 = W[k * 128 + n];
    float x1 = W[(k + 1) * 128 + n];
    __nv_bfloat16 h0 = __float2bfloat16(x0);
    __nv_bfloat16 h1 = __float2bfloat16(x1);
    __nv_bfloat16 l0 = __float2bfloat16(x0 - __bfloat162float(h0));
    __nv_bfloat16 l1 = __float2bfloat16(x1 - __bfloat162float(h1));
    wt[id]        = (unsigned int)__bfloat16_as_ushort(h0) | ((unsigned int)__bfloat16_as_ushort(h1) << 16);
    wt[8192 + id] = (unsigned int)__bfloat16_as_ushort(l0) | ((unsigned int)__bfloat16_as_ushort(l1) << 16);
}

// ---------------- packed f32x2 helpers ----------------
__device__ __forceinline__ void addx2(unsigned long long& a, unsigned long long b) {
    asm("add.rn.f32x2 %0, %0, %1;" : "+l"(a) : "l"(b));
}
__device__ __forceinline__ unsigned long long mulx2(unsigned long long a, unsigned long long b) {
    unsigned long long r;
    asm("mul.rn.f32x2 %0, %1, %2;" : "=l"(r) : "l"(a), "l"(b));
    return r;
}
__device__ __forceinline__ unsigned long long packx2(float lo, float hi) {
    unsigned long long r;
    asm("mov.b64 %0, {%1, %2};" : "=l"(r) : "f"(lo), "f"(hi));
    return r;
}

// ---------------- polynomial filter: acc = sum_{k=0..3} S^k x ----------------
// One CTA (1024 threads) per (graph, 32-col slice). Quarter-warp (8 lanes x float4)
// per row, 4 rows per quarter, degree-sorted assignment. Neighbor lists in SMEM
// (offset LDS is a quarter-warp broadcast -> ~free on the crossbar) AND 32 warps/SM.
// nbr byte offset for row == row*PADN*2 == row*128 == u-row byte offset (roff).
#define FS 32
#define UROWS 513                        // row 512 = zero row
#define POLY_NBR  0
#define POLY_U0   (POLY_NBR + NN_*PADN*2)         // +65536
#define POLY_U1   (POLY_U0 + UROWS*FS*4)          // +65664
#define POLY_DINV (POLY_U1 + UROWS*FS*4)          // +65664
#define POLY_PC   (POLY_DINV + NN_*4)
#define POLY_SMEM (POLY_PC + NN_*4)               // 200960 B

__global__ void __launch_bounds__(1024, 1) poly_kernel(const float* __restrict__ xin) {
    extern __shared__ unsigned char smraw[];
    unsigned short* nbr_s = (unsigned short*)(smraw + POLY_NBR);
    float* ubuf0   = (float*)(smraw + POLY_U0);
    float* ubuf1   = (float*)(smraw + POLY_U1);
    float* dinv_s  = (float*)(smraw + POLY_DINV);
    unsigned* pc_s = (unsigned*)(smraw + POLY_PC);

    int g  = blockIdx.y;
    int fb = blockIdx.x * FS;
    int tid = threadIdx.x, w = tid >> 5, lane = tid & 31;
    int q  = lane >> 3;            // quarter-warp id 0..3
    int li = lane & 7;             // lane in quarter; cols li*4..li*4+3
    int pbase = w * 4 + q;         // sorted position base (0..127); rows at m*128+pbase

    // copy neighbor lists into smem (uint4 = 8 u16 per load)
    {
        const uint4* src = (const uint4*)&g_nbr[(size_t)g * 512 * PADN];
        uint4* dst = (uint4*)nbr_s;
        for (int i = tid; i < 512 * PADN / 8; i += 1024) dst[i] = src[i];
    }
    if (tid < 512) {
        dinv_s[tid] = g_dinv[g * 512 + tid];
        pc_s[tid]   = g_pc[g * 512 + tid];
    }
    // zero row 512 of both u buffers
    if (tid >= 512 && tid < 544) ubuf0[512 * FS + (tid - 512)] = 0.0f;
    else if (tid >= 544 && tid < 576) ubuf1[512 * FS + (tid - 544)] = 0.0f;
    __syncthreads();

    // per-m row metadata in registers (fixed across hops)
    int roff[4];                       // row*128 : byte offset into nbr AND u rows
    int cntm[4];
    unsigned long long ddm[4];
    unsigned long long accA[4], accB[4];

    const char* xbase = (const char*)(xin + (size_t)g * 512 * FF + fb) + li * 16;
#pragma unroll
    for (int m = 0; m < 4; m++) {
        unsigned pc = pc_s[m * 128 + pbase];
        int row = pc & 0xffffu;
        cntm[m] = pc >> 16;
        roff[m] = row * 128;
        float d = dinv_s[row];
        ddm[m] = packx2(d, d);
        ulonglong2 xv = *(const ulonglong2*)(xbase + (size_t)row * 512);
        accA[m] = xv.x; accB[m] = xv.y;
        ulonglong2 uw;
        uw.x = mulx2(ddm[m], accA[m]);
        uw.y = mulx2(ddm[m], accB[m]);
        *(ulonglong2*)((char*)ubuf0 + roff[m] + li * 16) = uw;
    }
    __syncthreads();

    float* ucur = ubuf0;
    float* unew = ubuf1;
#pragma unroll 1
    for (int hop = 0; hop < 3; hop++) {
        const char* ucb = (const char*)ucur + li * 16;   // gather base (+node*128)
#pragma unroll
        for (int m = 0; m < 4; m++) {
            const uint2* rowp = (const uint2*)((const char*)nbr_s + roff[m]);
            int cnt4 = cntm[m];
            unsigned long long sa0 = 0ull, sa1 = 0ull, sb0 = 0ull, sb1 = 0ull;
#pragma unroll 1
            for (int e = 0; e < cnt4; e += 4) {
                uint2 pk = rowp[e >> 2];
                unsigned o0 = pk.x & 0xffffu, o1 = pk.x >> 16;
                unsigned o2 = pk.y & 0xffffu, o3 = pk.y >> 16;
                ulonglong2 v0 = *(const ulonglong2*)(ucb + ((size_t)o0 << 4));
                ulonglong2 v1 = *(const ulonglong2*)(ucb + ((size_t)o1 << 4));
                ulonglong2 v2 = *(const ulonglong2*)(ucb + ((size_t)o2 << 4));
                ulonglong2 v3 = *(const ulonglong2*)(ucb + ((size_t)o3 << 4));
                addx2(sa0, v0.x); addx2(sa1, v0.y);
                addx2(sb0, v1.x); addx2(sb1, v1.y);
                addx2(sa0, v2.x); addx2(sa1, v2.y);
                addx2(sb0, v3.x); addx2(sb1, v3.y);
            }
            addx2(sa0, sb0); addx2(sa1, sb1);
            unsigned long long zn0 = mulx2(ddm[m], sa0);
            unsigned long long zn1 = mulx2(ddm[m], sa1);
            addx2(accA[m], zn0); addx2(accB[m], zn1);
            if (hop < 2) {
                ulonglong2 uw;
                uw.x = mulx2(ddm[m], zn0);
                uw.y = mulx2(ddm[m], zn1);
                *(ulonglong2*)((char*)unew + roff[m] + li * 16) = uw;
            }
        }
        __syncthreads();
        float* t = ucur; ucur = unew; unew = t;
    }

    char* ybase = (char*)(g_acc + (size_t)g * 512 * FF + fb) + li * 16;
#pragma unroll
    for (int m = 0; m < 4; m++) {
        ulonglong2 ov; ov.x = accA[m]; ov.y = accB[m];
        *(ulonglong2*)(ybase + (size_t)roff[m] * 4) = ov;
    }
}

// ---------------- mma.sync GEMM + bias + relu ----------------
#define ASTR 136
#define GMM_AH 0
#define GMM_AL (GMM_AH + 128*ASTR*2)
#define GMM_BH (GMM_AL + 128*ASTR*2)
#define GMM_BL (GMM_BH + 128*ASTR*2)
#define GMM_BIAS (GMM_BL + 128*ASTR*2)
#define GEMM_MMA_SMEM (GMM_BIAS + 128*4)

__device__ __forceinline__ void mma16816(float* c, const unsigned* a, const unsigned* b) {
    asm volatile(
        "mma.sync.aligned.m16n8k16.row.col.f32.bf16.bf16.f32 "
        "{%0,%1,%2,%3}, {%4,%5,%6,%7}, {%8,%9}, {%0,%1,%2,%3};"
        : "+f"(c[0]), "+f"(c[1]), "+f"(c[2]), "+f"(c[3])
        : "r"(a[0]), "r"(a[1]), "r"(a[2]), "r"(a[3]), "r"(b[0]), "r"(b[1]));
}

__global__ void __launch_bounds__(256, 1) gemm_mma_kernel(
        const float* __restrict__ A, const unsigned int* __restrict__ wt,
        const float* __restrict__ bias, float* __restrict__ Y) {
    extern __shared__ unsigned char smg[];
    unsigned short* Ah = (unsigned short*)(smg + GMM_AH);
    unsigned short* Al = (unsigned short*)(smg + GMM_AL);
    unsigned short* Bh = (unsigned short*)(smg + GMM_BH);
    unsigned short* Bl = (unsigned short*)(smg + GMM_BL);
    float* bias_s = (float*)(smg + GMM_BIAS);

    int tid = threadIdx.x;
    int lane = tid & 31;
    int w = tid >> 5;
    int wr = w & 3;
    int wc = w >> 2;
    size_t rowbase = (size_t)blockIdx.x * 128;

    for (int idx = tid; idx < 8192; idx += 256) {
        int n = idx >> 6, p = idx & 63;
        *(unsigned int*)&Bh[n * ASTR + 2 * p] = wt[idx];
        *(unsigned int*)&Bl[n * ASTR + 2 * p] = wt[8192 + idx];
    }
    for (int idx = tid; idx < 8192; idx += 256) {
        int r = idx >> 6, p = idx & 63;
        float2 x = *(const float2*)(A + (rowbase + r) * 128 + 2 * p);
        __nv_bfloat16 h0 = __float2bfloat16(x.x);
        __nv_bfloat16 h1 = __float2bfloat16(x.y);
        __nv_bfloat16 l0 = __float2bfloat16(x.x - __bfloat162float(h0));
        __nv_bfloat16 l1 = __float2bfloat16(x.y - __bfloat162float(h1));
        *(unsigned int*)&Ah[r * ASTR + 2 * p] =
            (unsigned int)__bfloat16_as_ushort(h0) | ((unsigned int)__bfloat16_as_ushort(h1) << 16);
        *(unsigned int*)&Al[r * ASTR + 2 * p] =
            (unsigned int)__bfloat16_as_ushort(l0) | ((unsigned int)__bfloat16_as_ushort(l1) << 16);
    }
    if (tid < 128) bias_s[tid] = bias[tid];
    __syncthreads();

    float acc[2][8][4];
#pragma unroll
    for (int mt = 0; mt < 2; mt++)
#pragma unroll
        for (int nt = 0; nt < 8; nt++)
#pragma unroll
            for (int p = 0; p < 4; p++) acc[mt][nt][p] = 0.0f;

    int frow = lane >> 2;
    int fcolb = 2 * (lane & 3);

#pragma unroll
    for (int kk = 0; kk < 8; kk++) {
        int kc = fcolb + 16 * kk;
        unsigned ah[2][4], al[2][4], bh[8][2], bl[8][2];
#pragma unroll
        for (int mt = 0; mt < 2; mt++) {
            int r0 = 32 * wr + 16 * mt + frow;
            ah[mt][0] = *(const unsigned*)&Ah[r0 * ASTR + kc];
            ah[mt][1] = *(const unsigned*)&Ah[(r0 + 8) * ASTR + kc];
            ah[mt][2] = *(const unsigned*)&Ah[r0 * ASTR + kc + 8];
            ah[mt][3] = *(const unsigned*)&Ah[(r0 + 8) * ASTR + kc + 8];
            al[mt][0] = *(const unsigned*)&Al[r0 * ASTR + kc];
            al[mt][1] = *(const unsigned*)&Al[(r0 + 8) * ASTR + kc];
            al[mt][2] = *(const unsigned*)&Al[r0 * ASTR + kc + 8];
            al[mt][3] = *(const unsigned*)&Al[(r0 + 8) * ASTR + kc + 8];
        }
#pragma unroll
        for (int nt = 0; nt < 8; nt++) {
            int n0 = 64 * wc + 8 * nt + frow;
            bh[nt][0] = *(const unsigned*)&Bh[n0 * ASTR + kc];
            bh[nt][1] = *(const unsigned*)&Bh[n0 * ASTR + kc + 8];
            bl[nt][0] = *(const unsigned*)&Bl[n0 * ASTR + kc];
            bl[nt][1] = *(const unsigned*)&Bl[n0 * ASTR + kc + 8];
        }
#pragma unroll
        for (int mt = 0; mt < 2; mt++)
#pragma unroll
            for (int nt = 0; nt < 8; nt++) {
                mma16816(acc[mt][nt], ah[mt], bh[nt]);
                mma16816(acc[mt][nt], ah[mt], bl[nt]);
                mma16816(acc[mt][nt], al[mt], bh[nt]);
            }
    }

#pragma unroll
    for (int mt = 0; mt < 2; mt++) {
        size_t r0 = rowbase + 32 * wr + 16 * mt + frow;
#pragma unroll
        for (int nt = 0; nt < 8; nt++) {
            int col = 64 * wc + 8 * nt + fcolb;
            float b0 = bias_s[col], b1 = bias_s[col + 1];
            float2 v0, v1;
            float t;
            t = acc[mt][nt][0] + b0; v0.x = t > 0 ? t : 0;
            t = acc[mt][nt][1] + b1; v0.y = t > 0 ? t : 0;
            t = acc[mt][nt][2] + b0; v1.x = t > 0 ? t : 0;
            t = acc[mt][nt][3] + b1; v1.y = t > 0 ? t : 0;
            *(float2*)(Y + r0 * 128 + col)       = v0;
            *(float2*)(Y + (r0 + 8) * 128 + col) = v1;
        }
    }
}

// ---------------- head ----------------
__global__ void __launch_bounds__(512) head_kernel(
        const float* __restrict__ Wr1, const float* __restrict__ br1,
        const float* __restrict__ Wr2, const float* __restrict__ br2,
        float* __restrict__ out) {
    __shared__ float part[4][128];
    __shared__ float hs[128];
    __shared__ float rs[64];
    int g = blockIdx.x;
    int tid = threadIdx.x;
    int f = tid & 127, q = tid >> 7;

    const float* yg = g_y + (size_t)g * 512 * 128;
    float s = 0.0f;
    for (int n = q * 128; n < q * 128 + 128; n++) s += yg[(size_t)n * 128 + f];
    part[q][f] = s;
    __syncthreads();

    if (tid < 128)
        hs[tid] = (part[0][tid] + part[1][tid] + part[2][tid] + part[3][tid]) * (1.0f / 512.0f);
    __syncthreads();

    if (tid < 64) {
        float a = br1[tid];
        for (int k = 0; k < 128; k++) a += hs[k] * Wr1[k * 64 + tid];
        rs[tid] = a > 0 ? a : 0;
    }
    __syncthreads();

    if (tid == 0) {
        float a = br2[0];
        for (int o = 0; o < 64; o++) a += rs[o] * Wr2[o];
        out[g] = a;
    }
}

// ---------------- launch ----------------
extern "C" void kernel_launch(void* const* d_in, const int* in_sizes, int n_in,
                              void* d_out, int out_size) {
    const float* X   = (const float*)d_in[0];
    const int*   ei  = (const int*)d_in[2];
    const float* W1  = (const float*)d_in[3];
    const float* b1  = (const float*)d_in[4];
    const float* W2  = (const float*)d_in[5];
    const float* b2  = (const float*)d_in[6];
    const float* Wr1 = (const float*)d_in[7];
    const float* br1 = (const float*)d_in[8];
    const float* Wr2 = (const float*)d_in[9];
    const float* br2 = (const float*)d_in[10];
    float* out = (float*)d_out;

    cudaFuncSetAttribute(poly_kernel, cudaFuncAttributeMaxDynamicSharedMemorySize, POLY_SMEM);
    cudaFuncSetAttribute(gemm_mma_kernel, cudaFuncAttributeMaxDynamicSharedMemorySize, GEMM_MMA_SMEM);

    void* yaddr = nullptr;  cudaGetSymbolAddress(&yaddr, g_y);
    float* Yp = (float*)yaddr;
    void* aaddr = nullptr;  cudaGetSymbolAddress(&aaddr, g_acc);
    const float* Ap = (const float*)aaddr;
    void* w1addr = nullptr; cudaGetSymbolAddress(&w1addr, g_wt1);
    void* w2addr = nullptr; cudaGetSymbolAddress(&w2addr, g_wt2);

    // adjacency (rebuilt every call; deterministic)
    clear_adj_kernel<<<ADJ_WORDS / 256, 256>>>();
    build_adj_kernel<<<ETOT / 256, 256>>>(ei);
    expand_kernel<<<NTOT / 256, 256>>>();
    sort_kernel<<<BG, 512>>>();
    prep_w_kernel<<<64, 256>>>(W1, W2, (unsigned int*)w1addr, (unsigned int*)w2addr);

    dim3 pgrid(FF / FS, BG);

    // layer 1
    poly_kernel<<<pgrid, 1024, POLY_SMEM>>>(X);
    gemm_mma_kernel<<<NTOT / 128, 256, GEMM_MMA_SMEM>>>(Ap, (const unsigned int*)w1addr, b1, Yp);
    // layer 2
    poly_kernel<<<pgrid, 1024, POLY_SMEM>>>(Yp);
    gemm_mma_kernel<<<NTOT / 128, 256, GEMM_MMA_SMEM>>>(Ap, (const unsigned int*)w2addr, b2, Yp);
    // head
    head_kernel<<<BG, 512>>>(Wr1, br1, Wr2, br2, out);
}

// round 9
// speedup vs baseline: 1.0248x; 1.0248x over previous
#include <cuda_runtime.h>
#include <cuda_bf16.h>

// Problem constants (fixed by the reference)
#define BG   128              // graphs
#define NN_  512              // nodes per graph
#define FF   128              // feature dim
#define DEG  16
#define ETOT (BG*NN_*DEG)     // 1,048,576 edges
#define NTOT (BG*NN_)         // 65,536 nodes
#define ADJ_WORDS (BG*NN_*(NN_/32))  // 4MB bitmask
#define PADN 64               // padded neighbor-list stride (multiple of 4)

// -------- device-global scratch (no allocations allowed) --------
__device__ unsigned int   g_adj[ADJ_WORDS];
__device__ unsigned int   g_nbr32[(size_t)NTOT * PADN + 4];  // byte offsets node*128 (+pad for prefetch)
__device__ float          g_dinv[NTOT];
__device__ unsigned int   g_pc[NTOT];                   // degree-sorted: node | cnt4<<16
__device__ float g_acc[(size_t)NTOT * FF];   // 32MB
__device__ float g_y[(size_t)NTOT * FF];     // 32MB
__device__ unsigned int g_wt1[16384];        // W1^T split: hi pairs / lo pairs
__device__ unsigned int g_wt2[16384];        // W2^T split

// ---------------- adjacency build ----------------
__global__ void clear_adj_kernel() {
    int i = blockIdx.x * blockDim.x + threadIdx.x;
    if (i < ADJ_WORDS) g_adj[i] = 0u;
}

__global__ void build_adj_kernel(const int* __restrict__ ei) {
    int e = blockIdx.x * blockDim.x + threadIdx.x;
    if (e >= ETOT) return;
    int src = ei[e];
    int dst = ei[ETOT + e];
    int g  = src >> 9;         // N = 512
    int si = src & 511;
    int di = dst & 511;
    atomicOr(&g_adj[(g * 512 + si) * 16 + (di >> 5)], 1u << (di & 31));
}

// Fused: expand bitmask -> u32 byte-offset lists (node*128), dinv,
// then per-graph counting sort by degree -> g_pc. One block per graph.
__global__ void __launch_bounds__(512) expand_sort_kernel() {
    __shared__ unsigned hist[17];
    __shared__ unsigned basep[17];
    int g = blockIdx.x, tid = threadIdx.x;
    int i = g * 512 + tid;

    int cnt = 0;
    unsigned* row = &g_nbr32[(size_t)i * PADN];
#pragma unroll
    for (int w = 0; w < 16; w++) {
        unsigned int bits = g_adj[i * 16 + w];
        while (bits) {
            int b = __ffs(bits) - 1;
            bits &= bits - 1;
            if (cnt < PADN) row[cnt] = (unsigned)((w * 32 + b) << 7);  // node*128
            cnt++;
        }
    }
    if (cnt > PADN) cnt = PADN;
    g_dinv[i] = (cnt > 0) ? rsqrtf((float)cnt) : 0.0f;
    int cnt4 = (cnt + 3) & ~3;
    for (int e = cnt; e < cnt4; e++) row[e] = 512u << 7;   // zero row at node 512

    if (tid < 17) hist[tid] = 0;
    __syncthreads();
    int bin = cnt4 >> 2;   // 0..16
    atomicAdd(&hist[bin], 1);
    __syncthreads();
    if (tid == 0) {
        unsigned s = 0;
        for (int k = 0; k < 17; k++) { basep[k] = s; s += hist[k]; }
    }
    __syncthreads();
    unsigned pos = atomicAdd(&basep[bin], 1);
    g_pc[g * 512 + pos] = (unsigned)tid | ((unsigned)cnt4 << 16);
}

// Transpose + hi/lo bf16 split of both weights in one launch.
__global__ void prep_w_kernel(const float* __restrict__ W1, const float* __restrict__ W2,
                              unsigned int* __restrict__ wt1, unsigned int* __restrict__ wt2) {
    int idx = blockIdx.x * blockDim.x + threadIdx.x;
    const float* W = (idx < 8192) ? W1 : W2;
    unsigned int* wt = (idx < 8192) ? wt1 : wt2;
    int id = idx & 8191;
    int n = id >> 6, k = (id & 63) * 2;
    float x0 = W[k * 128 + n];
    float x1 = W[(k + 1) * 128 + n];
    __nv_bfloat16 h0 = __float2bfloat16(x0);
    __nv_bfloat16 h1 = __float2bfloat16(x1);
    __nv_bfloat16 l0 = __float2bfloat16(x0 - __bfloat162float(h0));
    __nv_bfloat16 l1 = __float2bfloat16(x1 - __bfloat162float(h1));
    wt[id]        = (unsigned int)__bfloat16_as_ushort(h0) | ((unsigned int)__bfloat16_as_ushort(h1) << 16);
    wt[8192 + id] = (unsigned int)__bfloat16_as_ushort(l0) | ((unsigned int)__bfloat16_as_ushort(l1) << 16);
}

// ---------------- packed f32x2 helpers ----------------
__device__ __forceinline__ void addx2(unsigned long long& a, unsigned long long b) {
    asm("add.rn.f32x2 %0, %0, %1;" : "+l"(a) : "l"(b));
}
__device__ __forceinline__ unsigned long long mulx2(unsigned long long a, unsigned long long b) {
    unsigned long long r;
    asm("mul.rn.f32x2 %0, %1, %2;" : "=l"(r) : "l"(a), "l"(b));
    return r;
}
__device__ __forceinline__ unsigned long long packx2(float lo, float hi) {
    unsigned long long r;
    asm("mov.b64 %0, {%1, %2};" : "=l"(r) : "f"(lo), "f"(hi));
    return r;
}

// ---------------- polynomial filter: acc = sum_{k=0..3} S^k x ----------------
// One CTA (1024 threads) per (graph, 32-col slice). Quarter-warp (8 lanes x float4)
// per row, 4 rows per quarter, degree-sorted assignment. Neighbor offset lists
// streamed from gmem (L1) with one-iteration prefetch; offsets are pre-scaled
// u-row byte offsets (node*128) -> gather address is a single add.
#define FS 32
#define UROWS 513                        // row 512 = zero row
#define POLY_U0   0
#define POLY_U1   (POLY_U0 + UROWS*FS*4)          // +65664
#define POLY_DINV (POLY_U1 + UROWS*FS*4)          // +65664
#define POLY_PC   (POLY_DINV + NN_*4)
#define POLY_SMEM (POLY_PC + NN_*4)

__global__ void __launch_bounds__(1024, 1) poly_kernel(const float* __restrict__ xin) {
    extern __shared__ unsigned char smraw[];
    float* ubuf0   = (float*)(smraw + POLY_U0);
    float* ubuf1   = (float*)(smraw + POLY_U1);
    float* dinv_s  = (float*)(smraw + POLY_DINV);
    unsigned* pc_s = (unsigned*)(smraw + POLY_PC);

    int g  = blockIdx.y;
    int fb = blockIdx.x * FS;
    int tid = threadIdx.x, w = tid >> 5, lane = tid & 31;
    int q  = lane >> 3;            // quarter-warp id 0..3
    int li = lane & 7;             // lane in quarter; cols li*4..li*4+3
    int pbase = w * 4 + q;         // sorted position base (0..127); rows at m*128+pbase

    const char* nbr_base = (const char*)&g_nbr32[(size_t)g * 512 * PADN];

    if (tid < 512) {
        dinv_s[tid] = g_dinv[g * 512 + tid];
        pc_s[tid]   = g_pc[g * 512 + tid];
    }
    // zero row 512 of both u buffers
    if (tid >= 512 && tid < 544) ubuf0[512 * FS + (tid - 512)] = 0.0f;
    else if (tid >= 544 && tid < 576) ubuf1[512 * FS + (tid - 544)] = 0.0f;
    __syncthreads();

    // per-m row metadata in registers (fixed across hops)
    int roff[4];                       // row*128 : u-row byte offset
    int cntm[4];
    unsigned long long ddm[4];
    unsigned long long accA[4], accB[4];

    const char* xbase = (const char*)(xin + (size_t)g * 512 * FF + fb) + li * 16;
#pragma unroll
    for (int m = 0; m < 4; m++) {
        unsigned pc = pc_s[m * 128 + pbase];
        int row = pc & 0xffffu;
        cntm[m] = pc >> 16;
        roff[m] = row * 128;
        float d = dinv_s[row];
        ddm[m] = packx2(d, d);
        ulonglong2 xv = *(const ulonglong2*)(xbase + (size_t)row * 512);
        accA[m] = xv.x; accB[m] = xv.y;
        ulonglong2 uw;
        uw.x = mulx2(ddm[m], accA[m]);
        uw.y = mulx2(ddm[m], accB[m]);
        *(ulonglong2*)((char*)ubuf0 + roff[m] + li * 16) = uw;
    }
    __syncthreads();

    float* ucur = ubuf0;
    float* unew = ubuf1;
#pragma unroll 1
    for (int hop = 0; hop < 3; hop++) {
        const char* ucb = (const char*)ucur + li * 16;   // gather base (+row byte offset)
#pragma unroll
        for (int m = 0; m < 4; m++) {
            // nbr row byte offset = row*PADN*4 = roff*2
            const uint4* rowp = (const uint4*)(nbr_base + ((size_t)roff[m] << 1));
            int cnt4 = cntm[m];
            unsigned long long sa0 = 0ull, sa1 = 0ull, sb0 = 0ull, sb1 = 0ull;
            uint4 pk = __ldg(rowp);
#pragma unroll 1
            for (int e = 0; e < cnt4; e += 4) {
                uint4 nx = __ldg(rowp + (e >> 2) + 1);   // prefetch (padded; safe)
                ulonglong2 v0 = *(const ulonglong2*)(ucb + pk.x);
                ulonglong2 v1 = *(const ulonglong2*)(ucb + pk.y);
                ulonglong2 v2 = *(const ulonglong2*)(ucb + pk.z);
                ulonglong2 v3 = *(const ulonglong2*)(ucb + pk.w);
                addx2(sa0, v0.x); addx2(sa1, v0.y);
                addx2(sb0, v1.x); addx2(sb1, v1.y);
                addx2(sa0, v2.x); addx2(sa1, v2.y);
                addx2(sb0, v3.x); addx2(sb1, v3.y);
                pk = nx;
            }
            addx2(sa0, sb0); addx2(sa1, sb1);
            unsigned long long zn0 = mulx2(ddm[m], sa0);
            unsigned long long zn1 = mulx2(ddm[m], sa1);
            addx2(accA[m], zn0); addx2(accB[m], zn1);
            if (hop < 2) {
                ulonglong2 uw;
                uw.x = mulx2(ddm[m], zn0);
                uw.y = mulx2(ddm[m], zn1);
                *(ulonglong2*)((char*)unew + roff[m] + li * 16) = uw;
            }
        }
        __syncthreads();
        float* t = ucur; ucur = unew; unew = t;
    }

    char* ybase = (char*)(g_acc + (size_t)g * 512 * FF + fb) + li * 16;
#pragma unroll
    for (int m = 0; m < 4; m++) {
        ulonglong2 ov; ov.x = accA[m]; ov.y = accB[m];
        *(ulonglong2*)(ybase + (size_t)roff[m] * 4) = ov;
    }
}

// ---------------- mma.sync GEMM + bias + relu ----------------
#define ASTR 136
#define GMM_AH 0
#define GMM_AL (GMM_AH + 128*ASTR*2)
#define GMM_BH (GMM_AL + 128*ASTR*2)
#define GMM_BL (GMM_BH + 128*ASTR*2)
#define GMM_BIAS (GMM_BL + 128*ASTR*2)
#define GEMM_MMA_SMEM (GMM_BIAS + 128*4)

__device__ __forceinline__ void mma16816(float* c, const unsigned* a, const unsigned* b) {
    asm volatile(
        "mma.sync.aligned.m16n8k16.row.col.f32.bf16.bf16.f32 "
        "{%0,%1,%2,%3}, {%4,%5,%6,%7}, {%8,%9}, {%0,%1,%2,%3};"
        : "+f"(c[0]), "+f"(c[1]), "+f"(c[2]), "+f"(c[3])
        : "r"(a[0]), "r"(a[1]), "r"(a[2]), "r"(a[3]), "r"(b[0]), "r"(b[1]));
}

__global__ void __launch_bounds__(256, 1) gemm_mma_kernel(
        const float* __restrict__ A, const unsigned int* __restrict__ wt,
        const float* __restrict__ bias, float* __restrict__ Y) {
    extern __shared__ unsigned char smg[];
    unsigned short* Ah = (unsigned short*)(smg + GMM_AH);
    unsigned short* Al = (unsigned short*)(smg + GMM_AL);
    unsigned short* Bh = (unsigned short*)(smg + GMM_BH);
    unsigned short* Bl = (unsigned short*)(smg + GMM_BL);
    float* bias_s = (float*)(smg + GMM_BIAS);

    int tid = threadIdx.x;
    int lane = tid & 31;
    int w = tid >> 5;
    int wr = w & 3;
    int wc = w >> 2;
    size_t rowbase = (size_t)blockIdx.x * 128;

    for (int idx = tid; idx < 8192; idx += 256) {
        int n = idx >> 6, p = idx & 63;
        *(unsigned int*)&Bh[n * ASTR + 2 * p] = wt[idx];
        *(unsigned int*)&Bl[n * ASTR + 2 * p] = wt[8192 + idx];
    }
    for (int idx = tid; idx < 8192; idx += 256) {
        int r = idx >> 6, p = idx & 63;
        float2 x = *(const float2*)(A + (rowbase + r) * 128 + 2 * p);
        __nv_bfloat16 h0 = __float2bfloat16(x.x);
        __nv_bfloat16 h1 = __float2bfloat16(x.y);
        __nv_bfloat16 l0 = __float2bfloat16(x.x - __bfloat162float(h0));
        __nv_bfloat16 l1 = __float2bfloat16(x.y - __bfloat162float(h1));
        *(unsigned int*)&Ah[r * ASTR + 2 * p] =
            (unsigned int)__bfloat16_as_ushort(h0) | ((unsigned int)__bfloat16_as_ushort(h1) << 16);
        *(unsigned int*)&Al[r * ASTR + 2 * p] =
            (unsigned int)__bfloat16_as_ushort(l0) | ((unsigned int)__bfloat16_as_ushort(l1) << 16);
    }
    if (tid < 128) bias_s[tid] = bias[tid];
    __syncthreads();

    float acc[2][8][4];
#pragma unroll
    for (int mt = 0; mt < 2; mt++)
#pragma unroll
        for (int nt = 0; nt < 8; nt++)
#pragma unroll
            for (int p = 0; p < 4; p++) acc[mt][nt][p] = 0.0f;

    int frow = lane >> 2;
    int fcolb = 2 * (lane & 3);

#pragma unroll
    for (int kk = 0; kk < 8; kk++) {
        int kc = fcolb + 16 * kk;
        unsigned ah[2][4], al[2][4], bh[8][2], bl[8][2];
#pragma unroll
        for (int mt = 0; mt < 2; mt++) {
            int r0 = 32 * wr + 16 * mt + frow;
            ah[mt][0] = *(const unsigned*)&Ah[r0 * ASTR + kc];
            ah[mt][1] = *(const unsigned*)&Ah[(r0 + 8) * ASTR + kc];
            ah[mt][2] = *(const unsigned*)&Ah[r0 * ASTR + kc + 8];
            ah[mt][3] = *(const unsigned*)&Ah[(r0 + 8) * ASTR + kc + 8];
            al[mt][0] = *(const unsigned*)&Al[r0 * ASTR + kc];
            al[mt][1] = *(const unsigned*)&Al[(r0 + 8) * ASTR + kc];
            al[mt][2] = *(const unsigned*)&Al[r0 * ASTR + kc + 8];
            al[mt][3] = *(const unsigned*)&Al[(r0 + 8) * ASTR + kc + 8];
        }
#pragma unroll
        for (int nt = 0; nt < 8; nt++) {
            int n0 = 64 * wc + 8 * nt + frow;
            bh[nt][0] = *(const unsigned*)&Bh[n0 * ASTR + kc];
            bh[nt][1] = *(const unsigned*)&Bh[n0 * ASTR + kc + 8];
            bl[nt][0] = *(const unsigned*)&Bl[n0 * ASTR + kc];
            bl[nt][1] = *(const unsigned*)&Bl[n0 * ASTR + kc + 8];
        }
#pragma unroll
        for (int mt = 0; mt < 2; mt++)
#pragma unroll
            for (int nt = 0; nt < 8; nt++) {
                mma16816(acc[mt][nt], ah[mt], bh[nt]);
                mma16816(acc[mt][nt], ah[mt], bl[nt]);
                mma16816(acc[mt][nt], al[mt], bh[nt]);
            }
    }

#pragma unroll
    for (int mt = 0; mt < 2; mt++) {
        size_t r0 = rowbase + 32 * wr + 16 * mt + frow;
#pragma unroll
        for (int nt = 0; nt < 8; nt++) {
            int col = 64 * wc + 8 * nt + fcolb;
            float b0 = bias_s[col], b1 = bias_s[col + 1];
            float2 v0, v1;
            float t;
            t = acc[mt][nt][0] + b0; v0.x = t > 0 ? t : 0;
            t = acc[mt][nt][1] + b1; v0.y = t > 0 ? t : 0;
            t = acc[mt][nt][2] + b0; v1.x = t > 0 ? t : 0;
            t = acc[mt][nt][3] + b1; v1.y = t > 0 ? t : 0;
            *(float2*)(Y + r0 * 128 + col)       = v0;
            *(float2*)(Y + (r0 + 8) * 128 + col) = v1;
        }
    }
}

// ---------------- head ----------------
__global__ void __launch_bounds__(512) head_kernel(
        const float* __restrict__ Wr1, const float* __restrict__ br1,
        const float* __restrict__ Wr2, const float* __restrict__ br2,
        float* __restrict__ out) {
    __shared__ float part[4][128];
    __shared__ float hs[128];
    __shared__ float rs[64];
    int g = blockIdx.x;
    int tid = threadIdx.x;
    int f = tid & 127, q = tid >> 7;

    const float* yg = g_y + (size_t)g * 512 * 128;
    float s = 0.0f;
    for (int n = q * 128; n < q * 128 + 128; n++) s += yg[(size_t)n * 128 + f];
    part[q][f] = s;
    __syncthreads();

    if (tid < 128)
        hs[tid] = (part[0][tid] + part[1][tid] + part[2][tid] + part[3][tid]) * (1.0f / 512.0f);
    __syncthreads();

    if (tid < 64) {
        float a = br1[tid];
        for (int k = 0; k < 128; k++) a += hs[k] * Wr1[k * 64 + tid];
        rs[tid] = a > 0 ? a : 0;
    }
    __syncthreads();

    if (tid == 0) {
        float a = br2[0];
        for (int o = 0; o < 64; o++) a += rs[o] * Wr2[o];
        out[g] = a;
    }
}

// ---------------- launch ----------------
extern "C" void kernel_launch(void* const* d_in, const int* in_sizes, int n_in,
                              void* d_out, int out_size) {
    const float* X   = (const float*)d_in[0];
    const int*   ei  = (const int*)d_in[2];
    const float* W1  = (const float*)d_in[3];
    const float* b1  = (const float*)d_in[4];
    const float* W2  = (const float*)d_in[5];
    const float* b2  = (const float*)d_in[6];
    const float* Wr1 = (const float*)d_in[7];
    const float* br1 = (const float*)d_in[8];
    const float* Wr2 = (const float*)d_in[9];
    const float* br2 = (const float*)d_in[10];
    float* out = (float*)d_out;

    cudaFuncSetAttribute(poly_kernel, cudaFuncAttributeMaxDynamicSharedMemorySize, POLY_SMEM);
    cudaFuncSetAttribute(gemm_mma_kernel, cudaFuncAttributeMaxDynamicSharedMemorySize, GEMM_MMA_SMEM);

    void* yaddr = nullptr;  cudaGetSymbolAddress(&yaddr, g_y);
    float* Yp = (float*)yaddr;
    void* aaddr = nullptr;  cudaGetSymbolAddress(&aaddr, g_acc);
    const float* Ap = (const float*)aaddr;
    void* w1addr = nullptr; cudaGetSymbolAddress(&w1addr, g_wt1);
    void* w2addr = nullptr; cudaGetSymbolAddress(&w2addr, g_wt2);

    // adjacency (rebuilt every call; deterministic)
    clear_adj_kernel<<<ADJ_WORDS / 256, 256>>>();
    build_adj_kernel<<<ETOT / 256, 256>>>(ei);
    expand_sort_kernel<<<BG, 512>>>();
    prep_w_kernel<<<64, 256>>>(W1, W2, (unsigned int*)w1addr, (unsigned int*)w2addr);

    dim3 pgrid(FF / FS, BG);

    // layer 1
    poly_kernel<<<pgrid, 1024, POLY_SMEM>>>(X);
    gemm_mma_kernel<<<NTOT / 128, 256, GEMM_MMA_SMEM>>>(Ap, (const unsigned int*)w1addr, b1, Yp);
    // layer 2
    poly_kernel<<<pgrid, 1024, POLY_SMEM>>>(Yp);
    gemm_mma_kernel<<<NTOT / 128, 256, GEMM_MMA_SMEM>>>(Ap, (const unsigned int*)w2addr, b2, Yp);
    // head
    head_kernel<<<BG, 512>>>(Wr1, br1, Wr2, br2, out);
}

// round 10
// speedup vs baseline: 1.0337x; 1.0087x over previous
#include <cuda_runtime.h>
#include <cuda_bf16.h>

// Problem constants (fixed by the reference)
#define BG   128              // graphs
#define NN_  512              // nodes per graph
#define FF   128              // feature dim
#define DEG  16
#define ETOT (BG*NN_*DEG)     // 1,048,576 edges
#define NTOT (BG*NN_)         // 65,536 nodes
#define ADJ_WORDS (BG*NN_*(NN_/32))  // 4MB bitmask
#define PADN 64               // padded neighbor-list stride (multiple of 4)

// -------- device-global scratch (no allocations allowed) --------
__device__ unsigned int   g_adj[ADJ_WORDS];
__device__ unsigned int   g_nbr32[(size_t)NTOT * PADN + 4];  // byte offsets node*128 (+pad for prefetch)
__device__ float          g_dinv[NTOT];
__device__ unsigned int   g_pc[NTOT];                   // degree-sorted: node | cnt4<<16
__device__ float g_acc[(size_t)NTOT * FF];   // 32MB
__device__ float g_y[(size_t)NTOT * FF];     // 32MB
__device__ unsigned int g_wt1[16384];        // W1^T split: hi pairs / lo pairs
__device__ unsigned int g_wt2[16384];        // W2^T split

// ---------------- adjacency build ----------------
__global__ void clear_adj_kernel() {
    int i = blockIdx.x * blockDim.x + threadIdx.x;
    if (i < ADJ_WORDS) g_adj[i] = 0u;
}

__global__ void build_adj_kernel(const int* __restrict__ ei) {
    int e = blockIdx.x * blockDim.x + threadIdx.x;
    if (e >= ETOT) return;
    int src = ei[e];
    int dst = ei[ETOT + e];
    int g  = src >> 9;         // N = 512
    int si = src & 511;
    int di = dst & 511;
    atomicOr(&g_adj[(g * 512 + si) * 16 + (di >> 5)], 1u << (di & 31));
}

// Fused: expand bitmask -> u32 byte-offset lists (node*128), dinv,
// then per-graph counting sort by degree -> g_pc. One block per graph.
__global__ void __launch_bounds__(512) expand_sort_kernel() {
    __shared__ unsigned hist[17];
    __shared__ unsigned basep[17];
    int g = blockIdx.x, tid = threadIdx.x;
    int i = g * 512 + tid;

    int cnt = 0;
    unsigned* row = &g_nbr32[(size_t)i * PADN];
#pragma unroll
    for (int w = 0; w < 16; w++) {
        unsigned int bits = g_adj[i * 16 + w];
        while (bits) {
            int b = __ffs(bits) - 1;
            bits &= bits - 1;
            if (cnt < PADN) row[cnt] = (unsigned)((w * 32 + b) << 7);  // node*128
            cnt++;
        }
    }
    if (cnt > PADN) cnt = PADN;
    g_dinv[i] = (cnt > 0) ? rsqrtf((float)cnt) : 0.0f;
    int cnt4 = (cnt + 3) & ~3;
    for (int e = cnt; e < cnt4; e++) row[e] = 512u << 7;   // zero row at node 512

    if (tid < 17) hist[tid] = 0;
    __syncthreads();
    int bin = cnt4 >> 2;   // 0..16
    atomicAdd(&hist[bin], 1);
    __syncthreads();
    if (tid == 0) {
        unsigned s = 0;
        for (int k = 0; k < 17; k++) { basep[k] = s; s += hist[k]; }
    }
    __syncthreads();
    unsigned pos = atomicAdd(&basep[bin], 1);
    g_pc[g * 512 + pos] = (unsigned)tid | ((unsigned)cnt4 << 16);
}

// Transpose + hi/lo bf16 split of both weights in one launch.
__global__ void prep_w_kernel(const float* __restrict__ W1, const float* __restrict__ W2,
                              unsigned int* __restrict__ wt1, unsigned int* __restrict__ wt2) {
    int idx = blockIdx.x * blockDim.x + threadIdx.x;
    const float* W = (idx < 8192) ? W1 : W2;
    unsigned int* wt = (idx < 8192) ? wt1 : wt2;
    int id = idx & 8191;
    int n = id >> 6, k = (id & 63) * 2;
    float x0 = W[k * 128 + n];
    float x1 = W[(k + 1) * 128 + n];
    __nv_bfloat16 h0 = __float2bfloat16(x0);
    __nv_bfloat16 h1 = __float2bfloat16(x1);
    __nv_bfloat16 l0 = __float2bfloat16(x0 - __bfloat162float(h0));
    __nv_bfloat16 l1 = __float2bfloat16(x1 - __bfloat162float(h1));
    wt[id]        = (unsigned int)__bfloat16_as_ushort(h0) | ((unsigned int)__bfloat16_as_ushort(h1) << 16);
    wt[8192 + id] = (unsigned int)__bfloat16_as_ushort(l0) | ((unsigned int)__bfloat16_as_ushort(l1) << 16);
}

// ---------------- packed f32x2 helpers ----------------
__device__ __forceinline__ void addx2(unsigned long long& a, unsigned long long b) {
    asm("add.rn.f32x2 %0, %0, %1;" : "+l"(a) : "l"(b));
}
__device__ __forceinline__ unsigned long long mulx2(unsigned long long a, unsigned long long b) {
    unsigned long long r;
    asm("mul.rn.f32x2 %0, %1, %2;" : "=l"(r) : "l"(a), "l"(b));
    return r;
}
__device__ __forceinline__ unsigned long long packx2(float lo, float hi) {
    unsigned long long r;
    asm("mov.b64 %0, {%1, %2};" : "=l"(r) : "f"(lo), "f"(hi));
    return r;
}

// ---------------- polynomial filter: acc = sum_{k=0..3} S^k x ----------------
// One CTA (1024 threads) per (graph, 32-col slice). Quarter-warp (8 lanes x float4)
// per row. Degree-sorted positions with SERPENTINE warp assignment: even m-iters
// map warps low->high degree, odd m-iters high->low, so every warp's total edge
// count is ~equal (the per-hop __syncthreads waits on the slowest warp).
#define FS 32
#define UROWS 513                        // row 512 = zero row
#define POLY_U0   0
#define POLY_U1   (POLY_U0 + UROWS*FS*4)          // +65664
#define POLY_DINV (POLY_U1 + UROWS*FS*4)          // +65664
#define POLY_PC   (POLY_DINV + NN_*4)
#define POLY_SMEM (POLY_PC + NN_*4)

__global__ void __launch_bounds__(1024, 1) poly_kernel(const float* __restrict__ xin) {
    extern __shared__ unsigned char smraw[];
    float* ubuf0   = (float*)(smraw + POLY_U0);
    float* ubuf1   = (float*)(smraw + POLY_U1);
    float* dinv_s  = (float*)(smraw + POLY_DINV);
    unsigned* pc_s = (unsigned*)(smraw + POLY_PC);

    int g  = blockIdx.y;
    int fb = blockIdx.x * FS;
    int tid = threadIdx.x, w = tid >> 5, lane = tid & 31;
    int q  = lane >> 3;            // quarter-warp id 0..3
    int li = lane & 7;             // lane in quarter; cols li*4..li*4+3

    const char* nbr_base = (const char*)&g_nbr32[(size_t)g * 512 * PADN];

    if (tid < 512) {
        dinv_s[tid] = g_dinv[g * 512 + tid];
        pc_s[tid]   = g_pc[g * 512 + tid];
    }
    // zero row 512 of both u buffers
    if (tid >= 512 && tid < 544) ubuf0[512 * FS + (tid - 512)] = 0.0f;
    else if (tid >= 544 && tid < 576) ubuf1[512 * FS + (tid - 544)] = 0.0f;
    __syncthreads();

    // per-m row metadata in registers (fixed across hops)
    int roff[4];                       // row*128 : u-row byte offset
    int cntm[4];
    unsigned long long ddm[4];
    unsigned long long accA[4], accB[4];

    const char* xbase = (const char*)(xin + (size_t)g * 512 * FF + fb) + li * 16;
#pragma unroll
    for (int m = 0; m < 4; m++) {
        // serpentine: even m ascending by warp, odd m descending -> balanced totals
        int pos = m * 128 + ((m & 1) ? (124 - 4 * w) : (4 * w)) + q;
        unsigned pc = pc_s[pos];
        int row = pc & 0xffffu;
        cntm[m] = pc >> 16;
        roff[m] = row * 128;
        float d = dinv_s[row];
        ddm[m] = packx2(d, d);
        ulonglong2 xv = *(const ulonglong2*)(xbase + (size_t)row * 512);
        accA[m] = xv.x; accB[m] = xv.y;
        ulonglong2 uw;
        uw.x = mulx2(ddm[m], accA[m]);
        uw.y = mulx2(ddm[m], accB[m]);
        *(ulonglong2*)((char*)ubuf0 + roff[m] + li * 16) = uw;
    }
    __syncthreads();

    float* ucur = ubuf0;
    float* unew = ubuf1;
#pragma unroll 1
    for (int hop = 0; hop < 3; hop++) {
        const char* ucb = (const char*)ucur + li * 16;   // gather base (+row byte offset)
#pragma unroll
        for (int m = 0; m < 4; m++) {
            // nbr row byte offset = row*PADN*4 = roff*2
            const uint4* rowp = (const uint4*)(nbr_base + ((size_t)roff[m] << 1));
            int cnt4 = cntm[m];
            unsigned long long sa0 = 0ull, sa1 = 0ull, sb0 = 0ull, sb1 = 0ull;
            uint4 pk = __ldg(rowp);
#pragma unroll 1
            for (int e = 0; e < cnt4; e += 4) {
                uint4 nx = __ldg(rowp + (e >> 2) + 1);   // prefetch (padded; safe)
                ulonglong2 v0 = *(const ulonglong2*)(ucb + pk.x);
                ulonglong2 v1 = *(const ulonglong2*)(ucb + pk.y);
                ulonglong2 v2 = *(const ulonglong2*)(ucb + pk.z);
                ulonglong2 v3 = *(const ulonglong2*)(ucb + pk.w);
                addx2(sa0, v0.x); addx2(sa1, v0.y);
                addx2(sb0, v1.x); addx2(sb1, v1.y);
                addx2(sa0, v2.x); addx2(sa1, v2.y);
                addx2(sb0, v3.x); addx2(sb1, v3.y);
                pk = nx;
            }
            addx2(sa0, sb0); addx2(sa1, sb1);
            unsigned long long zn0 = mulx2(ddm[m], sa0);
            unsigned long long zn1 = mulx2(ddm[m], sa1);
            addx2(accA[m], zn0); addx2(accB[m], zn1);
            if (hop < 2) {
                ulonglong2 uw;
                uw.x = mulx2(ddm[m], zn0);
                uw.y = mulx2(ddm[m], zn1);
                *(ulonglong2*)((char*)unew + roff[m] + li * 16) = uw;
            }
        }
        __syncthreads();
        float* t = ucur; ucur = unew; unew = t;
    }

    char* ybase = (char*)(g_acc + (size_t)g * 512 * FF + fb) + li * 16;
#pragma unroll
    for (int m = 0; m < 4; m++) {
        ulonglong2 ov; ov.x = accA[m]; ov.y = accB[m];
        *(ulonglong2*)(ybase + (size_t)roff[m] * 4) = ov;
    }
}

// ---------------- mma.sync GEMM + bias + relu ----------------
#define ASTR 136
#define GMM_AH 0
#define GMM_AL (GMM_AH + 128*ASTR*2)
#define GMM_BH (GMM_AL + 128*ASTR*2)
#define GMM_BL (GMM_BH + 128*ASTR*2)
#define GMM_BIAS (GMM_BL + 128*ASTR*2)
#define GEMM_MMA_SMEM (GMM_BIAS + 128*4)

__device__ __forceinline__ void mma16816(float* c, const unsigned* a, const unsigned* b) {
    asm volatile(
        "mma.sync.aligned.m16n8k16.row.col.f32.bf16.bf16.f32 "
        "{%0,%1,%2,%3}, {%4,%5,%6,%7}, {%8,%9}, {%0,%1,%2,%3};"
        : "+f"(c[0]), "+f"(c[1]), "+f"(c[2]), "+f"(c[3])
        : "r"(a[0]), "r"(a[1]), "r"(a[2]), "r"(a[3]), "r"(b[0]), "r"(b[1]));
}

__global__ void __launch_bounds__(256, 1) gemm_mma_kernel(
        const float* __restrict__ A, const unsigned int* __restrict__ wt,
        const float* __restrict__ bias, float* __restrict__ Y) {
    extern __shared__ unsigned char smg[];
    unsigned short* Ah = (unsigned short*)(smg + GMM_AH);
    unsigned short* Al = (unsigned short*)(smg + GMM_AL);
    unsigned short* Bh = (unsigned short*)(smg + GMM_BH);
    unsigned short* Bl = (unsigned short*)(smg + GMM_BL);
    float* bias_s = (float*)(smg + GMM_BIAS);

    int tid = threadIdx.x;
    int lane = tid & 31;
    int w = tid >> 5;
    int wr = w & 3;
    int wc = w >> 2;
    size_t rowbase = (size_t)blockIdx.x * 128;

    for (int idx = tid; idx < 8192; idx += 256) {
        int n = idx >> 6, p = idx & 63;
        *(unsigned int*)&Bh[n * ASTR + 2 * p] = wt[idx];
        *(unsigned int*)&Bl[n * ASTR + 2 * p] = wt[8192 + idx];
    }
    for (int idx = tid; idx < 8192; idx += 256) {
        int r = idx >> 6, p = idx & 63;
        float2 x = *(const float2*)(A + (rowbase + r) * 128 + 2 * p);
        __nv_bfloat16 h0 = __float2bfloat16(x.x);
        __nv_bfloat16 h1 = __float2bfloat16(x.y);
        __nv_bfloat16 l0 = __float2bfloat16(x.x - __bfloat162float(h0));
        __nv_bfloat16 l1 = __float2bfloat16(x.y - __bfloat162float(h1));
        *(unsigned int*)&Ah[r * ASTR + 2 * p] =
            (unsigned int)__bfloat16_as_ushort(h0) | ((unsigned int)__bfloat16_as_ushort(h1) << 16);
        *(unsigned int*)&Al[r * ASTR + 2 * p] =
            (unsigned int)__bfloat16_as_ushort(l0) | ((unsigned int)__bfloat16_as_ushort(l1) << 16);
    }
    if (tid < 128) bias_s[tid] = bias[tid];
    __syncthreads();

    float acc[2][8][4];
#pragma unroll
    for (int mt = 0; mt < 2; mt++)
#pragma unroll
        for (int nt = 0; nt < 8; nt++)
#pragma unroll
            for (int p = 0; p < 4; p++) acc[mt][nt][p] = 0.0f;

    int frow = lane >> 2;
    int fcolb = 2 * (lane & 3);

#pragma unroll
    for (int kk = 0; kk < 8; kk++) {
        int kc = fcolb + 16 * kk;
        unsigned ah[2][4], al[2][4], bh[8][2], bl[8][2];
#pragma unroll
        for (int mt = 0; mt < 2; mt++) {
            int r0 = 32 * wr + 16 * mt + frow;
            ah[mt][0] = *(const unsigned*)&Ah[r0 * ASTR + kc];
            ah[mt][1] = *(const unsigned*)&Ah[(r0 + 8) * ASTR + kc];
            ah[mt][2] = *(const unsigned*)&Ah[r0 * ASTR + kc + 8];
            ah[mt][3] = *(const unsigned*)&Ah[(r0 + 8) * ASTR + kc + 8];
            al[mt][0] = *(const unsigned*)&Al[r0 * ASTR + kc];
            al[mt][1] = *(const unsigned*)&Al[(r0 + 8) * ASTR + kc];
            al[mt][2] = *(const unsigned*)&Al[r0 * ASTR + kc + 8];
            al[mt][3] = *(const unsigned*)&Al[(r0 + 8) * ASTR + kc + 8];
        }
#pragma unroll
        for (int nt = 0; nt < 8; nt++) {
            int n0 = 64 * wc + 8 * nt + frow;
            bh[nt][0] = *(const unsigned*)&Bh[n0 * ASTR + kc];
            bh[nt][1] = *(const unsigned*)&Bh[n0 * ASTR + kc + 8];
            bl[nt][0] = *(const unsigned*)&Bl[n0 * ASTR + kc];
            bl[nt][1] = *(const unsigned*)&Bl[n0 * ASTR + kc + 8];
        }
#pragma unroll
        for (int mt = 0; mt < 2; mt++)
#pragma unroll
            for (int nt = 0; nt < 8; nt++) {
                mma16816(acc[mt][nt], ah[mt], bh[nt]);
                mma16816(acc[mt][nt], ah[mt], bl[nt]);
                mma16816(acc[mt][nt], al[mt], bh[nt]);
            }
    }

#pragma unroll
    for (int mt = 0; mt < 2; mt++) {
        size_t r0 = rowbase + 32 * wr + 16 * mt + frow;
#pragma unroll
        for (int nt = 0; nt < 8; nt++) {
            int col = 64 * wc + 8 * nt + fcolb;
            float b0 = bias_s[col], b1 = bias_s[col + 1];
            float2 v0, v1;
            float t;
            t = acc[mt][nt][0] + b0; v0.x = t > 0 ? t : 0;
            t = acc[mt][nt][1] + b1; v0.y = t > 0 ? t : 0;
            t = acc[mt][nt][2] + b0; v1.x = t > 0 ? t : 0;
            t = acc[mt][nt][3] + b1; v1.y = t > 0 ? t : 0;
            *(float2*)(Y + r0 * 128 + col)       = v0;
            *(float2*)(Y + (r0 + 8) * 128 + col) = v1;
        }
    }
}

// ---------------- head ----------------
__global__ void __launch_bounds__(512) head_kernel(
        const float* __restrict__ Wr1, const float* __restrict__ br1,
        const float* __restrict__ Wr2, const float* __restrict__ br2,
        float* __restrict__ out) {
    __shared__ float part[4][128];
    __shared__ float hs[128];
    __shared__ float rs[64];
    int g = blockIdx.x;
    int tid = threadIdx.x;
    int f = tid & 127, q = tid >> 7;

    const float* yg = g_y + (size_t)g * 512 * 128;
    float s = 0.0f;
    for (int n = q * 128; n < q * 128 + 128; n++) s += yg[(size_t)n * 128 + f];
    part[q][f] = s;
    __syncthreads();

    if (tid < 128)
        hs[tid] = (part[0][tid] + part[1][tid] + part[2][tid] + part[3][tid]) * (1.0f / 512.0f);
    __syncthreads();

    if (tid < 64) {
        float a = br1[tid];
        for (int k = 0; k < 128; k++) a += hs[k] * Wr1[k * 64 + tid];
        rs[tid] = a > 0 ? a : 0;
    }
    __syncthreads();

    if (tid == 0) {
        float a = br2[0];
        for (int o = 0; o < 64; o++) a += rs[o] * Wr2[o];
        out[g] = a;
    }
}

// ---------------- launch ----------------
extern "C" void kernel_launch(void* const* d_in, const int* in_sizes, int n_in,
                              void* d_out, int out_size) {
    const float* X   = (const float*)d_in[0];
    const int*   ei  = (const int*)d_in[2];
    const float* W1  = (const float*)d_in[3];
    const float* b1  = (const float*)d_in[4];
    const float* W2  = (const float*)d_in[5];
    const float* b2  = (const float*)d_in[6];
    const float* Wr1 = (const float*)d_in[7];
    const float* br1 = (const float*)d_in[8];
    const float* Wr2 = (const float*)d_in[9];
    const float* br2 = (const float*)d_in[10];
    float* out = (float*)d_out;

    cudaFuncSetAttribute(poly_kernel, cudaFuncAttributeMaxDynamicSharedMemorySize, POLY_SMEM);
    cudaFuncSetAttribute(gemm_mma_kernel, cudaFuncAttributeMaxDynamicSharedMemorySize, GEMM_MMA_SMEM);

    void* yaddr = nullptr;  cudaGetSymbolAddress(&yaddr, g_y);
    float* Yp = (float*)yaddr;
    void* aaddr = nullptr;  cudaGetSymbolAddress(&aaddr, g_acc);
    const float* Ap = (const float*)aaddr;
    void* w1addr = nullptr; cudaGetSymbolAddress(&w1addr, g_wt1);
    void* w2addr = nullptr; cudaGetSymbolAddress(&w2addr, g_wt2);

    // adjacency (rebuilt every call; deterministic)
    clear_adj_kernel<<<ADJ_WORDS / 256, 256>>>();
    build_adj_kernel<<<ETOT / 256, 256>>>(ei);
    expand_sort_kernel<<<BG, 512>>>();
    prep_w_kernel<<<64, 256>>>(W1, W2, (unsigned int*)w1addr, (unsigned int*)w2addr);

    dim3 pgrid(FF / FS, BG);

    // layer 1
    poly_kernel<<<pgrid, 1024, POLY_SMEM>>>(X);
    gemm_mma_kernel<<<NTOT / 128, 256, GEMM_MMA_SMEM>>>(Ap, (const unsigned int*)w1addr, b1, Yp);
    // layer 2
    poly_kernel<<<pgrid, 1024, POLY_SMEM>>>(Yp);
    gemm_mma_kernel<<<NTOT / 128, 256, GEMM_MMA_SMEM>>>(Ap, (const unsigned int*)w2addr, b2, Yp);
    // head
    head_kernel<<<BG, 512>>>(Wr1, br1, Wr2, br2, out);
}

// round 11
// speedup vs baseline: 1.1480x; 1.1106x over previous
#include <cuda_runtime.h>
#include <cuda_bf16.h>

// Problem constants (fixed by the reference)
#define BG   128              // graphs
#define NN_  512              // nodes per graph
#define FF   128              // feature dim
#define DEG  16
#define ETOT (BG*NN_*DEG)     // 1,048,576 edges
#define NTOT (BG*NN_)         // 65,536 nodes
#define ADJ_WORDS (BG*NN_*(NN_/32))  // 4MB bitmask
#define PADN 64               // padded neighbor-list stride (multiple of 4)

// -------- device-global scratch (no allocations allowed) --------
__device__ unsigned int   g_adj[ADJ_WORDS];
__device__ unsigned int   g_nbr32[(size_t)NTOT * PADN + 4];  // byte offsets node*64 (+pad for prefetch)
__device__ float          g_dinv[NTOT];
__device__ unsigned int   g_pc[NTOT];                   // degree-sorted: node | cnt4<<16
__device__ float g_acc[(size_t)NTOT * FF];   // 32MB
__device__ float g_y[(size_t)NTOT * FF];     // 32MB
__device__ unsigned int g_wt1[16384];        // W1^T split: hi pairs / lo pairs
__device__ unsigned int g_wt2[16384];        // W2^T split

// ---------------- adjacency build ----------------
__global__ void build_adj_kernel(const int* __restrict__ ei) {
    int e = blockIdx.x * blockDim.x + threadIdx.x;
    if (e >= ETOT) return;
    int src = ei[e];
    int dst = ei[ETOT + e];
    int g  = src >> 9;         // N = 512
    int si = src & 511;
    int di = dst & 511;
    atomicOr(&g_adj[(g * 512 + si) * 16 + (di >> 5)], 1u << (di & 31));
}

// Fused: expand bitmask -> u32 byte-offset lists (node*64 = bf16 u-row offset),
// dinv, then per-graph counting sort by degree -> g_pc. One block per graph.
__global__ void __launch_bounds__(512) expand_sort_kernel() {
    __shared__ unsigned hist[17];
    __shared__ unsigned basep[17];
    int g = blockIdx.x, tid = threadIdx.x;
    int i = g * 512 + tid;

    int cnt = 0;
    unsigned* row = &g_nbr32[(size_t)i * PADN];
#pragma unroll
    for (int w = 0; w < 16; w++) {
        unsigned int bits = g_adj[i * 16 + w];
        while (bits) {
            int b = __ffs(bits) - 1;
            bits &= bits - 1;
            if (cnt < PADN) row[cnt] = (unsigned)((w * 32 + b) << 6);  // node*64
            cnt++;
        }
    }
    if (cnt > PADN) cnt = PADN;
    g_dinv[i] = (cnt > 0) ? rsqrtf((float)cnt) : 0.0f;
    int cnt4 = (cnt + 3) & ~3;
    for (int e = cnt; e < cnt4; e++) row[e] = 512u << 6;   // zero row at node 512

    if (tid < 17) hist[tid] = 0;
    __syncthreads();
    int bin = cnt4 >> 2;   // 0..16
    atomicAdd(&hist[bin], 1);
    __syncthreads();
    if (tid == 0) {
        unsigned s = 0;
        for (int k = 0; k < 17; k++) { basep[k] = s; s += hist[k]; }
    }
    __syncthreads();
    unsigned pos = atomicAdd(&basep[bin], 1);
    g_pc[g * 512 + pos] = (unsigned)tid | ((unsigned)cnt4 << 16);
}

// Transpose + hi/lo bf16 split of both weights in one launch.
__global__ void prep_w_kernel(const float* __restrict__ W1, const float* __restrict__ W2,
                              unsigned int* __restrict__ wt1, unsigned int* __restrict__ wt2) {
    int idx = blockIdx.x * blockDim.x + threadIdx.x;
    const float* W = (idx < 8192) ? W1 : W2;
    unsigned int* wt = (idx < 8192) ? wt1 : wt2;
    int id = idx & 8191;
    int n = id >> 6, k = (id & 63) * 2;
    float x0 = W[k * 128 + n];
    float x1 = W[(k + 1) * 128 + n];
    __nv_bfloat16 h0 = __float2bfloat16(x0);
    __nv_bfloat16 h1 = __float2bfloat16(x1);
    __nv_bfloat16 l0 = __float2bfloat16(x0 - __bfloat162float(h0));
    __nv_bfloat16 l1 = __float2bfloat16(x1 - __bfloat162float(h1));
    wt[id]        = (unsigned int)__bfloat16_as_ushort(h0) | ((unsigned int)__bfloat16_as_ushort(h1) << 16);
    wt[8192 + id] = (unsigned int)__bfloat16_as_ushort(l0) | ((unsigned int)__bfloat16_as_ushort(l1) << 16);
}

// ---------------- bf16 helpers ----------------
__device__ __forceinline__ unsigned pack_bf16x2(float lo, float hi) {
    unsigned r;
    asm("cvt.rn.bf16x2.f32 %0, %1, %2;" : "=r"(r) : "f"(hi), "f"(lo));
    return r;
}
// exact bf16 -> f32: lo = u<<16, hi = u & 0xffff0000
__device__ __forceinline__ float bf_lo(unsigned u) { return __uint_as_float(u << 16); }
__device__ __forceinline__ float bf_hi(unsigned u) { return __uint_as_float(u & 0xffff0000u); }

// ---------------- polynomial filter: acc = sum_{k=0..3} S^k x ----------------
// One CTA (1024 threads) per (graph, 32-col slice). Quarter-warp (8 lanes) per row;
// hop state u stored in BF16 (64B rows -> half the crossbar bytes of fp32).
// Accumulation fully fp32 (exact unpack via shift); only u storage is rounded.
// u-space recurrence: u0 = dinv*x ; hop: s = gather(u) [fp32 sum], z = dinv*s
// (acc += z, fp32), u' = dinv*z (rounded to bf16).
#define FS 32
#define UROWS 513                        // row 512 = zero row
#define UROWB 64                         // bf16 row bytes
#define POLY_U0   0
#define POLY_U1   (POLY_U0 + UROWS*UROWB)         // +32832
#define POLY_DINV (POLY_U1 + UROWS*UROWB)         // +32832
#define POLY_PC   (POLY_DINV + NN_*4)
#define POLY_SMEM (POLY_PC + NN_*4)               // ~69.7KB

__global__ void __launch_bounds__(1024, 1) poly_kernel(const float* __restrict__ xin) {
    extern __shared__ unsigned char smraw[];
    unsigned char* ubuf0 = smraw + POLY_U0;
    unsigned char* ubuf1 = smraw + POLY_U1;
    float* dinv_s  = (float*)(smraw + POLY_DINV);
    unsigned* pc_s = (unsigned*)(smraw + POLY_PC);

    int g  = blockIdx.y;
    int fb = blockIdx.x * FS;
    int tid = threadIdx.x, w = tid >> 5, lane = tid & 31;
    int q  = lane >> 3;            // quarter-warp id 0..3
    int li = lane & 7;             // lane in quarter; cols 4*li..4*li+3

    const char* nbr_base = (const char*)&g_nbr32[(size_t)g * 512 * PADN];

    if (tid < 512) {
        dinv_s[tid] = g_dinv[g * 512 + tid];
        pc_s[tid]   = g_pc[g * 512 + tid];
    }
    // zero row 512 (64B) of both u buffers
    if (tid >= 512 && tid < 528) *(unsigned*)(ubuf0 + 512 * UROWB + (tid - 512) * 4) = 0u;
    else if (tid >= 544 && tid < 560) *(unsigned*)(ubuf1 + 512 * UROWB + (tid - 544) * 4) = 0u;
    __syncthreads();

    // per-m row metadata in registers (fixed across hops)
    int roff[4];                       // row*64 : bf16 u-row byte offset
    int cntm[4];
    float dm[4];
    float acc[4][4];                   // fp32 accumulator, 4 cols per lane

    const char* xbase = (const char*)(xin + (size_t)g * 512 * FF + fb) + li * 16;
#pragma unroll
    for (int m = 0; m < 4; m++) {
        int pos = m * 128 + ((m & 1) ? (124 - 4 * w) : (4 * w)) + q;  // serpentine
        unsigned pc = pc_s[pos];
        int row = pc & 0xffffu;
        cntm[m] = pc >> 16;
        roff[m] = row << 6;
        float d = dinv_s[row];
        dm[m] = d;
        float4 xv = *(const float4*)(xbase + (size_t)roff[m] * 8);   // row*512 bytes
        acc[m][0] = xv.x; acc[m][1] = xv.y; acc[m][2] = xv.z; acc[m][3] = xv.w;
        uint2 uw;
        uw.x = pack_bf16x2(d * xv.x, d * xv.y);
        uw.y = pack_bf16x2(d * xv.z, d * xv.w);
        *(uint2*)(ubuf0 + roff[m] + li * 8) = uw;
    }
    __syncthreads();

    unsigned char* ucur = ubuf0;
    unsigned char* unew = ubuf1;
#pragma unroll 1
    for (int hop = 0; hop < 3; hop++) {
        const char* ucb = (const char*)ucur + li * 8;   // gather base (+row byte offset)
#pragma unroll
        for (int m = 0; m < 4; m++) {
            // nbr row byte offset = row*PADN*4 = roff*4
            const uint4* rowp = (const uint4*)(nbr_base + ((size_t)roff[m] << 2));
            int cnt4 = cntm[m];
            float s0 = 0.f, s1 = 0.f, s2 = 0.f, s3 = 0.f;
            uint4 pk = __ldg(rowp);
#pragma unroll 1
            for (int e = 0; e < cnt4; e += 4) {
                uint4 nx = __ldg(rowp + (e >> 2) + 1);   // prefetch (padded; safe)
                uint2 v0 = *(const uint2*)(ucb + pk.x);
                uint2 v1 = *(const uint2*)(ucb + pk.y);
                uint2 v2 = *(const uint2*)(ucb + pk.z);
                uint2 v3 = *(const uint2*)(ucb + pk.w);
                s0 += bf_lo(v0.x); s1 += bf_hi(v0.x); s2 += bf_lo(v0.y); s3 += bf_hi(v0.y);
                s0 += bf_lo(v1.x); s1 += bf_hi(v1.x); s2 += bf_lo(v1.y); s3 += bf_hi(v1.y);
                s0 += bf_lo(v2.x); s1 += bf_hi(v2.x); s2 += bf_lo(v2.y); s3 += bf_hi(v2.y);
                s0 += bf_lo(v3.x); s1 += bf_hi(v3.x); s2 += bf_lo(v3.y); s3 += bf_hi(v3.y);
                pk = nx;
            }
            float d = dm[m];
            float z0 = d * s0, z1 = d * s1, z2 = d * s2, z3 = d * s3;
            acc[m][0] += z0; acc[m][1] += z1; acc[m][2] += z2; acc[m][3] += z3;
            if (hop < 2) {
                uint2 uw;
                uw.x = pack_bf16x2(d * z0, d * z1);
                uw.y = pack_bf16x2(d * z2, d * z3);
                *(uint2*)(unew + roff[m] + li * 8) = uw;
            }
        }
        __syncthreads();
        unsigned char* t = ucur; ucur = unew; unew = t;
    }

    char* ybase = (char*)(g_acc + (size_t)g * 512 * FF + fb) + li * 16;
#pragma unroll
    for (int m = 0; m < 4; m++) {
        float4 ov;
        ov.x = acc[m][0]; ov.y = acc[m][1]; ov.z = acc[m][2]; ov.w = acc[m][3];
        *(float4*)(ybase + (size_t)roff[m] * 8) = ov;
    }
}

// ---------------- mma.sync GEMM + bias + relu ----------------
#define ASTR 136
#define GMM_AH 0
#define GMM_AL (GMM_AH + 128*ASTR*2)
#define GMM_BH (GMM_AL + 128*ASTR*2)
#define GMM_BL (GMM_BH + 128*ASTR*2)
#define GMM_BIAS (GMM_BL + 128*ASTR*2)
#define GEMM_MMA_SMEM (GMM_BIAS + 128*4)

__device__ __forceinline__ void mma16816(float* c, const unsigned* a, const unsigned* b) {
    asm volatile(
        "mma.sync.aligned.m16n8k16.row.col.f32.bf16.bf16.f32 "
        "{%0,%1,%2,%3}, {%4,%5,%6,%7}, {%8,%9}, {%0,%1,%2,%3};"
        : "+f"(c[0]), "+f"(c[1]), "+f"(c[2]), "+f"(c[3])
        : "r"(a[0]), "r"(a[1]), "r"(a[2]), "r"(a[3]), "r"(b[0]), "r"(b[1]));
}

__global__ void __launch_bounds__(256, 1) gemm_mma_kernel(
        const float* __restrict__ A, const unsigned int* __restrict__ wt,
        const float* __restrict__ bias, float* __restrict__ Y) {
    extern __shared__ unsigned char smg[];
    unsigned short* Ah = (unsigned short*)(smg + GMM_AH);
    unsigned short* Al = (unsigned short*)(smg + GMM_AL);
    unsigned short* Bh = (unsigned short*)(smg + GMM_BH);
    unsigned short* Bl = (unsigned short*)(smg + GMM_BL);
    float* bias_s = (float*)(smg + GMM_BIAS);

    int tid = threadIdx.x;
    int lane = tid & 31;
    int w = tid >> 5;
    int wr = w & 3;
    int wc = w >> 2;
    size_t rowbase = (size_t)blockIdx.x * 128;

    for (int idx = tid; idx < 8192; idx += 256) {
        int n = idx >> 6, p = idx & 63;
        *(unsigned int*)&Bh[n * ASTR + 2 * p] = wt[idx];
        *(unsigned int*)&Bl[n * ASTR + 2 * p] = wt[8192 + idx];
    }
    for (int idx = tid; idx < 8192; idx += 256) {
        int r = idx >> 6, p = idx & 63;
        float2 x = *(const float2*)(A + (rowbase + r) * 128 + 2 * p);
        __nv_bfloat16 h0 = __float2bfloat16(x.x);
        __nv_bfloat16 h1 = __float2bfloat16(x.y);
        __nv_bfloat16 l0 = __float2bfloat16(x.x - __bfloat162float(h0));
        __nv_bfloat16 l1 = __float2bfloat16(x.y - __bfloat162float(h1));
        *(unsigned int*)&Ah[r * ASTR + 2 * p] =
            (unsigned int)__bfloat16_as_ushort(h0) | ((unsigned int)__bfloat16_as_ushort(h1) << 16);
        *(unsigned int*)&Al[r * ASTR + 2 * p] =
            (unsigned int)__bfloat16_as_ushort(l0) | ((unsigned int)__bfloat16_as_ushort(l1) << 16);
    }
    if (tid < 128) bias_s[tid] = bias[tid];
    __syncthreads();

    float acc[2][8][4];
#pragma unroll
    for (int mt = 0; mt < 2; mt++)
#pragma unroll
        for (int nt = 0; nt < 8; nt++)
#pragma unroll
            for (int p = 0; p < 4; p++) acc[mt][nt][p] = 0.0f;

    int frow = lane >> 2;
    int fcolb = 2 * (lane & 3);

#pragma unroll
    for (int kk = 0; kk < 8; kk++) {
        int kc = fcolb + 16 * kk;
        unsigned ah[2][4], al[2][4], bh[8][2], bl[8][2];
#pragma unroll
        for (int mt = 0; mt < 2; mt++) {
            int r0 = 32 * wr + 16 * mt + frow;
            ah[mt][0] = *(const unsigned*)&Ah[r0 * ASTR + kc];
            ah[mt][1] = *(const unsigned*)&Ah[(r0 + 8) * ASTR + kc];
            ah[mt][2] = *(const unsigned*)&Ah[r0 * ASTR + kc + 8];
            ah[mt][3] = *(const unsigned*)&Ah[(r0 + 8) * ASTR + kc + 8];
            al[mt][0] = *(const unsigned*)&Al[r0 * ASTR + kc];
            al[mt][1] = *(const unsigned*)&Al[(r0 + 8) * ASTR + kc];
            al[mt][2] = *(const unsigned*)&Al[r0 * ASTR + kc + 8];
            al[mt][3] = *(const unsigned*)&Al[(r0 + 8) * ASTR + kc + 8];
        }
#pragma unroll
        for (int nt = 0; nt < 8; nt++) {
            int n0 = 64 * wc + 8 * nt + frow;
            bh[nt][0] = *(const unsigned*)&Bh[n0 * ASTR + kc];
            bh[nt][1] = *(const unsigned*)&Bh[n0 * ASTR + kc + 8];
            bl[nt][0] = *(const unsigned*)&Bl[n0 * ASTR + kc];
            bl[nt][1] = *(const unsigned*)&Bl[n0 * ASTR + kc + 8];
        }
#pragma unroll
        for (int mt = 0; mt < 2; mt++)
#pragma unroll
            for (int nt = 0; nt < 8; nt++) {
                mma16816(acc[mt][nt], ah[mt], bh[nt]);
                mma16816(acc[mt][nt], ah[mt], bl[nt]);
                mma16816(acc[mt][nt], al[mt], bh[nt]);
            }
    }

#pragma unroll
    for (int mt = 0; mt < 2; mt++) {
        size_t r0 = rowbase + 32 * wr + 16 * mt + frow;
#pragma unroll
        for (int nt = 0; nt < 8; nt++) {
            int col = 64 * wc + 8 * nt + fcolb;
            float b0 = bias_s[col], b1 = bias_s[col + 1];
            float2 v0, v1;
            float t;
            t = acc[mt][nt][0] + b0; v0.x = t > 0 ? t : 0;
            t = acc[mt][nt][1] + b1; v0.y = t > 0 ? t : 0;
            t = acc[mt][nt][2] + b0; v1.x = t > 0 ? t : 0;
            t = acc[mt][nt][3] + b1; v1.y = t > 0 ? t : 0;
            *(float2*)(Y + r0 * 128 + col)       = v0;
            *(float2*)(Y + (r0 + 8) * 128 + col) = v1;
        }
    }
}

// ---------------- head ----------------
__global__ void __launch_bounds__(512) head_kernel(
        const float* __restrict__ Wr1, const float* __restrict__ br1,
        const float* __restrict__ Wr2, const float* __restrict__ br2,
        float* __restrict__ out) {
    __shared__ float part[4][128];
    __shared__ float hs[128];
    __shared__ float rs[64];
    int g = blockIdx.x;
    int tid = threadIdx.x;
    int f = tid & 127, q = tid >> 7;

    const float* yg = g_y + (size_t)g * 512 * 128;
    float s = 0.0f;
    for (int n = q * 128; n < q * 128 + 128; n++) s += yg[(size_t)n * 128 + f];
    part[q][f] = s;
    __syncthreads();

    if (tid < 128)
        hs[tid] = (part[0][tid] + part[1][tid] + part[2][tid] + part[3][tid]) * (1.0f / 512.0f);
    __syncthreads();

    if (tid < 64) {
        float a = br1[tid];
        for (int k = 0; k < 128; k++) a += hs[k] * Wr1[k * 64 + tid];
        rs[tid] = a > 0 ? a : 0;
    }
    __syncthreads();

    if (tid == 0) {
        float a = br2[0];
        for (int o = 0; o < 64; o++) a += rs[o] * Wr2[o];
        out[g] = a;
    }
}

// ---------------- launch ----------------
extern "C" void kernel_launch(void* const* d_in, const int* in_sizes, int n_in,
                              void* d_out, int out_size) {
    const float* X   = (const float*)d_in[0];
    const int*   ei  = (const int*)d_in[2];
    const float* W1  = (const float*)d_in[3];
    const float* b1  = (const float*)d_in[4];
    const float* W2  = (const float*)d_in[5];
    const float* b2  = (const float*)d_in[6];
    const float* Wr1 = (const float*)d_in[7];
    const float* br1 = (const float*)d_in[8];
    const float* Wr2 = (const float*)d_in[9];
    const float* br2 = (const float*)d_in[10];
    float* out = (float*)d_out;

    cudaFuncSetAttribute(poly_kernel, cudaFuncAttributeMaxDynamicSharedMemorySize, POLY_SMEM);
    cudaFuncSetAttribute(gemm_mma_kernel, cudaFuncAttributeMaxDynamicSharedMemorySize, GEMM_MMA_SMEM);

    void* yaddr = nullptr;  cudaGetSymbolAddress(&yaddr, g_y);
    float* Yp = (float*)yaddr;
    void* aaddr = nullptr;  cudaGetSymbolAddress(&aaddr, g_acc);
    const float* Ap = (const float*)aaddr;
    void* w1addr = nullptr; cudaGetSymbolAddress(&w1addr, g_wt1);
    void* w2addr = nullptr; cudaGetSymbolAddress(&w2addr, g_wt2);
    void* adjaddr = nullptr; cudaGetSymbolAddress(&adjaddr, g_adj);

    // adjacency (rebuilt every call; deterministic)
    cudaMemsetAsync(adjaddr, 0, ADJ_WORDS * sizeof(unsigned int));
    build_adj_kernel<<<ETOT / 256, 256>>>(ei);
    expand_sort_kernel<<<BG, 512>>>();
    prep_w_kernel<<<64, 256>>>(W1, W2, (unsigned int*)w1addr, (unsigned int*)w2addr);

    dim3 pgrid(FF / FS, BG);

    // layer 1
    poly_kernel<<<pgrid, 1024, POLY_SMEM>>>(X);
    gemm_mma_kernel<<<NTOT / 128, 256, GEMM_MMA_SMEM>>>(Ap, (const unsigned int*)w1addr, b1, Yp);
    // layer 2
    poly_kernel<<<pgrid, 1024, POLY_SMEM>>>(Yp);
    gemm_mma_kernel<<<NTOT / 128, 256, GEMM_MMA_SMEM>>>(Ap, (const unsigned int*)w2addr, b2, Yp);
    // head
    head_kernel<<<BG, 512>>>(Wr1, br1, Wr2, br2, out);
}